// round 5
// baseline (speedup 1.0000x reference)
#include <cuda_runtime.h>
#include <cuda_bf16.h>
#include <cstdint>

#define NN 8192

// ---------------- scratch (device globals; no allocations) ------------------
__device__ __align__(128) __nv_bfloat16 g_xT[(size_t)256 * NN];     // x^T bf16
__device__ __align__(128) __nv_bfloat16 g_nx_hi[(size_t)NN * 512];  // [x1|x] hi
__device__ __align__(128) __nv_bfloat16 g_nx_lo[(size_t)NN * 512];  // [x1|x] lo
__device__ __align__(128) __nv_bfloat16 g_Wt_hi[768 * 512];         // W^T hi
__device__ __align__(128) __nv_bfloat16 g_Wt_lo[768 * 512];         // W^T lo

// ---------------- helpers ----------------------------------------------------
__device__ __forceinline__ uint32_t smem_u32(const void* p) {
    uint32_t a;
    asm("{ .reg .u64 t; cvta.to.shared.u64 t, %1; cvt.u32.u64 %0, t; }"
        : "=r"(a) : "l"(p));
    return a;
}
__device__ __forceinline__ void cp16(uint32_t dst, const void* src) {
    asm volatile("cp.async.cg.shared.global [%0], [%1], 16;" :: "r"(dst), "l"(src));
}
__device__ __forceinline__ void cp_commit() {
    asm volatile("cp.async.commit_group;" ::: "memory");
}
template <int N> __device__ __forceinline__ void cp_wait() {
    asm volatile("cp.async.wait_group %0;" :: "n"(N) : "memory");
}
__device__ __forceinline__ void sts8(uint32_t addr, uint32_t v0, uint32_t v1) {
    asm volatile("st.shared.v2.u32 [%0], {%1,%2};" :: "r"(addr), "r"(v0), "r"(v1)
                 : "memory");
}
__device__ __forceinline__ void ldsm4(uint32_t& r0, uint32_t& r1, uint32_t& r2,
                                      uint32_t& r3, uint32_t addr) {
    asm volatile("ldmatrix.sync.aligned.m8n8.x4.shared.b16 {%0,%1,%2,%3}, [%4];"
                 : "=r"(r0), "=r"(r1), "=r"(r2), "=r"(r3) : "r"(addr));
}
__device__ __forceinline__ void mma16816(float* c, const uint32_t* a,
                                         const uint32_t* b) {
    asm volatile(
        "mma.sync.aligned.m16n8k16.row.col.f32.bf16.bf16.f32 "
        "{%0,%1,%2,%3}, {%4,%5,%6,%7}, {%8,%9}, {%0,%1,%2,%3};"
        : "+f"(c[0]), "+f"(c[1]), "+f"(c[2]), "+f"(c[3])
        : "r"(a[0]), "r"(a[1]), "r"(a[2]), "r"(a[3]), "r"(b[0]), "r"(b[1]));
}

// smem tile geometry: rows padded to 80B (conflict-free ldmatrix), 128 rows
#define ROWB   80u
#define STG    10240u          // one stage of one operand (128*80)
#define BOFF   40960u          // B stages base (4 A stages first)

// warp-tile compute: 32(M) x 64(N) x 32(K) per call, accum c[2][8][4]
__device__ __forceinline__ void tile_compute(uint32_t aAddr, uint32_t bAddr,
                                             float (&c)[2][8][4]) {
#pragma unroll
    for (int kk = 0; kk < 2; ++kk) {
        uint32_t A[2][4], B[8][2];
        ldsm4(A[0][0], A[0][1], A[0][2], A[0][3], aAddr + kk * 32);
        ldsm4(A[1][0], A[1][1], A[1][2], A[1][3], aAddr + 1280 + kk * 32);
#pragma unroll
        for (int p = 0; p < 4; ++p) {
            uint32_t r0, r1, r2, r3;
            ldsm4(r0, r1, r2, r3, bAddr + p * 1280 + kk * 32);
            B[2 * p][0] = r0; B[2 * p][1] = r1;
            B[2 * p + 1][0] = r2; B[2 * p + 1][1] = r3;
        }
#pragma unroll
        for (int mt = 0; mt < 2; ++mt)
#pragma unroll
            for (int nt = 0; nt < 8; ++nt)
                mma16816(c[mt][nt], A[mt], B[nt]);
    }
}

// ---------------- prep kernels ----------------------------------------------
__global__ void k_prep_x(const float* __restrict__ x) {
    __shared__ float tile[32][33];
    const int n0 = blockIdx.x * 32, f0 = blockIdx.y * 32;
    const int tx = threadIdx.x, ty = threadIdx.y;
    float v = x[(size_t)(n0 + ty) * 256 + f0 + tx];
    tile[ty][tx] = v;
    __nv_bfloat16 h = __float2bfloat16(v);
    size_t o = (size_t)(n0 + ty) * 512 + 256 + f0 + tx;
    g_nx_hi[o] = h;
    g_nx_lo[o] = __float2bfloat16(v - __bfloat162float(h));
    __syncthreads();
    g_xT[(size_t)(f0 + ty) * NN + n0 + tx] = __float2bfloat16(tile[tx][ty]);
}

__global__ void k_prep_w(const float* __restrict__ w) {
    const int b = blockIdx.x;            // Wt row = k*256 + o
    const int k = b >> 8, o = b & 255;
    const float* src = w + (size_t)k * 512 * 256 + o;
    __nv_bfloat16* dh = g_Wt_hi + (size_t)b * 512;
    __nv_bfloat16* dl = g_Wt_lo + (size_t)b * 512;
    for (int f = threadIdx.x; f < 512; f += 256) {
        float v = src[(size_t)f * 256];
        __nv_bfloat16 h = __float2bfloat16(v);
        dh[f] = h;
        dl[f] = __float2bfloat16(v - __bfloat162float(h));
    }
}

// ---------------- GEMM1: x1 = (adj @ x) / deg --------------------------------
// grid 128 = 64 M-tiles x 2 N-tiles. K = 8192 in 256 chunks of 32.
// A: adj int32 LDG -> regs -> exact bf16 STS (2-deep reg pipeline) + degree.
// B: g_xT via cp.async, 4 stages.
__device__ __forceinline__ void g1_ldgA(const int* __restrict__ adj, int m0,
                                        int kt, int tid, int4* R) {
    const int4* p = (const int4*)(adj + (size_t)(m0 + (tid >> 1)) * NN +
                                  kt * 32 + (tid & 1) * 16);
    R[0] = p[0]; R[1] = p[1]; R[2] = p[2]; R[3] = p[3];
}
__device__ __forceinline__ void g1_stsA(uint32_t sbase, int s, int tid,
                                        const int4* R, int& cnt) {
    const uint32_t base = sbase + s * STG + (tid >> 1) * ROWB + (tid & 1) * 32;
#pragma unroll
    for (int j = 0; j < 4; ++j) {
        int4 v = R[j];
        cnt += (v.x == 1) + (v.y == 1) + (v.z == 1) + (v.w == 1);
        uint32_t o0 = ((v.x == 1) ? 0x3F80u : 0u) | ((v.y == 1) ? 0x3F800000u : 0u);
        uint32_t o1 = ((v.z == 1) ? 0x3F80u : 0u) | ((v.w == 1) ? 0x3F800000u : 0u);
        sts8(base + j * 8, o0, o1);
    }
}
__device__ __forceinline__ void g1_cpB(uint32_t sbase, int s, int kt, int n0,
                                       int tid) {
#pragma unroll
    for (int i = 0; i < 2; ++i) {
        int idx = tid + i * 256;
        int n = idx >> 2, cc = idx & 3;
        cp16(sbase + BOFF + s * STG + n * ROWB + cc * 16,
             g_xT + (size_t)(n0 + n) * NN + kt * 32 + cc * 8);
    }
}

__global__ void __launch_bounds__(256) k_gemm1(const int* __restrict__ adj) {
    extern __shared__ char smem[];
    __shared__ int sdeg[128];
    const uint32_t sbase = smem_u32(smem);
    const int tid = threadIdx.x, lane = tid & 31, wid = tid >> 5;
    const int wm = wid >> 1, wn = wid & 1;
    const int m0 = (blockIdx.x >> 1) * 128, n0 = (blockIdx.x & 1) * 128;
    if (tid < 128) sdeg[tid] = 0;

    int4 Ra[4], Rb[4];
    int cnt = 0;
    g1_ldgA(adj, m0, 0, tid, Ra);
    g1_ldgA(adj, m0, 1, tid, Rb);
    g1_cpB(sbase, 0, 0, n0, tid); cp_commit();
    g1_cpB(sbase, 1, 1, n0, tid); cp_commit();
    g1_cpB(sbase, 2, 2, n0, tid); cp_commit();
    g1_stsA(sbase, 0, tid, Ra, cnt);

    const uint32_t aAddr0 = sbase + (wm * 32 + (lane & 15)) * ROWB + (lane >> 4) * 16;
    const uint32_t bAddr0 = sbase + BOFF +
        (wn * 64 + ((lane >> 4) << 3) + (lane & 7)) * ROWB + ((lane >> 3) & 1) * 16;

    float c[2][8][4] = {};
    for (int it = 0; it < 256; ++it) {
        const int s = it & 3;
        cp_wait<2>();
        __syncthreads();
        if (it + 2 < 256) g1_ldgA(adj, m0, it + 2, tid, (it & 1) ? Rb : Ra);
        if (it + 3 < 256) g1_cpB(sbase, (it + 3) & 3, it + 3, n0, tid);
        if (it + 1 < 256) g1_stsA(sbase, (it + 1) & 3, tid, ((it + 1) & 1) ? Rb : Ra, cnt);
        cp_commit();
        tile_compute(aAddr0 + s * STG, bAddr0 + s * STG, c);
    }

    atomicAdd(&sdeg[tid >> 1], cnt);
    __syncthreads();

    // epilogue: /deg, hi/lo bf16 split into g_nx
    const int r = lane >> 2, q = lane & 3;
#pragma unroll
    for (int mt = 0; mt < 2; ++mt) {
        const int lr = wm * 32 + mt * 16 + r;
        const float inv0 = 1.0f / (float)sdeg[lr];
        const float inv1 = 1.0f / (float)sdeg[lr + 8];
        const size_t gm0 = (size_t)(m0 + lr), gm1 = gm0 + 8;
#pragma unroll
        for (int nt = 0; nt < 8; ++nt) {
            const int col = n0 + wn * 64 + nt * 8 + q * 2;
            float v0 = c[mt][nt][0] * inv0, v1 = c[mt][nt][1] * inv0;
            float v2 = c[mt][nt][2] * inv1, v3 = c[mt][nt][3] * inv1;
            __nv_bfloat16 h0 = __float2bfloat16(v0), h1 = __float2bfloat16(v1);
            __nv_bfloat16 h2 = __float2bfloat16(v2), h3 = __float2bfloat16(v3);
            *(uint32_t*)(g_nx_hi + gm0 * 512 + col) =
                ((uint32_t)__bfloat16_as_ushort(h1) << 16) | __bfloat16_as_ushort(h0);
            *(uint32_t*)(g_nx_hi + gm1 * 512 + col) =
                ((uint32_t)__bfloat16_as_ushort(h3) << 16) | __bfloat16_as_ushort(h2);
            __nv_bfloat16 l0 = __float2bfloat16(v0 - __bfloat162float(h0));
            __nv_bfloat16 l1 = __float2bfloat16(v1 - __bfloat162float(h1));
            __nv_bfloat16 l2 = __float2bfloat16(v2 - __bfloat162float(h2));
            __nv_bfloat16 l3 = __float2bfloat16(v3 - __bfloat162float(h3));
            *(uint32_t*)(g_nx_lo + gm0 * 512 + col) =
                ((uint32_t)__bfloat16_as_ushort(l1) << 16) | __bfloat16_as_ushort(l0);
            *(uint32_t*)(g_nx_lo + gm1 * 512 + col) =
                ((uint32_t)__bfloat16_as_ushort(l3) << 16) | __bfloat16_as_ushort(l2);
        }
    }
}

// ---------------- GEMM2: out[k] = nx @ W[k] + bias (3-term bf16 split) ------
// iters 0..15: hi*Whi (f=0..511); 16..31: hi*Wlo (f=0..511); 32..39: lo*Whi (f=256..511)
__device__ __forceinline__ void g2_cp(uint32_t sbase, int s, int it, int m0,
                                      int bn0, int tid) {
    const __nv_bfloat16 *Ap, *Bp;
    int f0;
    if (it < 16)      { Ap = g_nx_hi; Bp = g_Wt_hi; f0 = it * 32; }
    else if (it < 32) { Ap = g_nx_hi; Bp = g_Wt_lo; f0 = (it - 16) * 32; }
    else              { Ap = g_nx_lo; Bp = g_Wt_hi; f0 = 256 + (it - 32) * 32; }
#pragma unroll
    for (int i = 0; i < 2; ++i) {
        int idx = tid + i * 256;
        int rr = idx >> 2, cc = idx & 3;
        cp16(sbase + s * STG + rr * ROWB + cc * 16,
             Ap + (size_t)(m0 + rr) * 512 + f0 + cc * 8);
        cp16(sbase + BOFF + s * STG + rr * ROWB + cc * 16,
             Bp + (size_t)(bn0 + rr) * 512 + f0 + cc * 8);
    }
}

__global__ void __launch_bounds__(256, 2) k_gemm2(const float* __restrict__ bias,
                                                  float* __restrict__ out) {
    extern __shared__ char smem[];
    __shared__ float sbias[128];
    const uint32_t sbase = smem_u32(smem);
    const int tid = threadIdx.x, lane = tid & 31, wid = tid >> 5;
    const int wm = wid >> 1, wn = wid & 1;
    const int bx = blockIdx.x;
    const int m0 = (bx / 6) * 128;
    const int ntile = bx % 6;
    const int kh = ntile >> 1, o0 = (ntile & 1) * 128;
    const int bn0 = kh * 256 + o0;
    if (tid < 128) sbias[tid] = bias[o0 + tid];

    g2_cp(sbase, 0, 0, m0, bn0, tid); cp_commit();
    g2_cp(sbase, 1, 1, m0, bn0, tid); cp_commit();
    g2_cp(sbase, 2, 2, m0, bn0, tid); cp_commit();

    const uint32_t aAddr0 = sbase + (wm * 32 + (lane & 15)) * ROWB + (lane >> 4) * 16;
    const uint32_t bAddr0 = sbase + BOFF +
        (wn * 64 + ((lane >> 4) << 3) + (lane & 7)) * ROWB + ((lane >> 3) & 1) * 16;

    float c[2][8][4] = {};
    for (int it = 0; it < 40; ++it) {
        const int s = it & 3;
        cp_wait<2>();
        __syncthreads();
        if (it + 3 < 40) g2_cp(sbase, (it + 3) & 3, it + 3, m0, bn0, tid);
        cp_commit();
        tile_compute(aAddr0 + s * STG, bAddr0 + s * STG, c);
    }

    const int r = lane >> 2, q = lane & 3;
#pragma unroll
    for (int mt = 0; mt < 2; ++mt) {
        const int lr = wm * 32 + mt * 16 + r;
        const size_t gm0 = (size_t)(m0 + lr);
#pragma unroll
        for (int nt = 0; nt < 8; ++nt) {
            const int oc = wn * 64 + nt * 8 + q * 2;
            float2 va = make_float2(c[mt][nt][0] + sbias[oc],
                                    c[mt][nt][1] + sbias[oc + 1]);
            float2 vb = make_float2(c[mt][nt][2] + sbias[oc],
                                    c[mt][nt][3] + sbias[oc + 1]);
            *(float2*)(out + ((size_t)kh * NN + gm0) * 256 + o0 + oc) = va;
            *(float2*)(out + ((size_t)kh * NN + gm0 + 8) * 256 + o0 + oc) = vb;
        }
    }
}

// ---------------- launch -----------------------------------------------------
extern "C" void kernel_launch(void* const* d_in, const int* in_sizes, int n_in,
                              void* d_out, int out_size) {
    const float* x = nullptr;
    const int* adj = nullptr;
    const float* w = nullptr;
    const float* bias = nullptr;
    for (int i = 0; i < n_in; ++i) {
        long sz = in_sizes[i];
        if (sz == (long)NN * 256) x = (const float*)d_in[i];
        else if (sz == (long)NN * NN) adj = (const int*)d_in[i];
        else if (sz == 3L * 512 * 256) w = (const float*)d_in[i];
        else if (sz == 256) bias = (const float*)d_in[i];
    }
    float* out = (float*)d_out;

    cudaFuncSetAttribute(k_gemm1, cudaFuncAttributeMaxDynamicSharedMemorySize, 81920);
    cudaFuncSetAttribute(k_gemm2, cudaFuncAttributeMaxDynamicSharedMemorySize, 81920);

    k_prep_x<<<dim3(256, 8), dim3(32, 32)>>>(x);
    k_prep_w<<<768, 256>>>(w);
    k_gemm1<<<128, 256, 81920>>>(adj);
    k_gemm2<<<384, 256, 81920>>>(bias, out);
}

// round 6
// speedup vs baseline: 1.0301x; 1.0301x over previous
#include <cuda_runtime.h>
#include <cuda_bf16.h>
#include <cstdint>

#define NN 8192

// ---------------- scratch (device globals; no allocations) ------------------
__device__ __align__(128) __nv_bfloat16 g_xT[(size_t)256 * NN];     // x^T bf16
__device__ __align__(128) __nv_bfloat16 g_nx_hi[(size_t)NN * 512];  // [x1|x] hi
__device__ __align__(128) __nv_bfloat16 g_nx_lo[(size_t)NN * 512];  // [x1|x] lo
__device__ __align__(128) __nv_bfloat16 g_Wt_hi[768 * 512];         // W^T hi
__device__ __align__(128) __nv_bfloat16 g_Wt_lo[768 * 512];         // W^T lo

// ---------------- helpers ----------------------------------------------------
__device__ __forceinline__ uint32_t smem_u32(const void* p) {
    uint32_t a;
    asm("{ .reg .u64 t; cvta.to.shared.u64 t, %1; cvt.u32.u64 %0, t; }"
        : "=r"(a) : "l"(p));
    return a;
}
__device__ __forceinline__ void cp16(uint32_t dst, const void* src) {
    asm volatile("cp.async.cg.shared.global [%0], [%1], 16;" :: "r"(dst), "l"(src));
}
__device__ __forceinline__ void cp_commit() {
    asm volatile("cp.async.commit_group;" ::: "memory");
}
template <int N> __device__ __forceinline__ void cp_wait() {
    asm volatile("cp.async.wait_group %0;" :: "n"(N) : "memory");
}
__device__ __forceinline__ void sts16(uint32_t addr, uint32_t v0, uint32_t v1,
                                      uint32_t v2, uint32_t v3) {
    asm volatile("st.shared.v4.u32 [%0], {%1,%2,%3,%4};"
                 :: "r"(addr), "r"(v0), "r"(v1), "r"(v2), "r"(v3) : "memory");
}
__device__ __forceinline__ void ldsm4(uint32_t& r0, uint32_t& r1, uint32_t& r2,
                                      uint32_t& r3, uint32_t addr) {
    asm volatile("ldmatrix.sync.aligned.m8n8.x4.shared.b16 {%0,%1,%2,%3}, [%4];"
                 : "=r"(r0), "=r"(r1), "=r"(r2), "=r"(r3) : "r"(addr));
}
__device__ __forceinline__ void mma16816(float* c, const uint32_t* a,
                                         const uint32_t* b) {
    asm volatile(
        "mma.sync.aligned.m16n8k16.row.col.f32.bf16.bf16.f32 "
        "{%0,%1,%2,%3}, {%4,%5,%6,%7}, {%8,%9}, {%0,%1,%2,%3};"
        : "+f"(c[0]), "+f"(c[1]), "+f"(c[2]), "+f"(c[3])
        : "r"(a[0]), "r"(a[1]), "r"(a[2]), "r"(a[3]), "r"(b[0]), "r"(b[1]));
}

// warp-tile compute: 32(M) x 64(N) x (KK*16)(K), accum c[2][8][4]
template <int KK, int PITCH>
__device__ __forceinline__ void tile_compute(uint32_t aAddr, uint32_t bAddr,
                                             float (&c)[2][8][4]) {
#pragma unroll
    for (int kk = 0; kk < KK; ++kk) {
        uint32_t A[2][4], B[8][2];
        ldsm4(A[0][0], A[0][1], A[0][2], A[0][3], aAddr + kk * 32);
        ldsm4(A[1][0], A[1][1], A[1][2], A[1][3], aAddr + 16 * PITCH + kk * 32);
#pragma unroll
        for (int p = 0; p < 4; ++p) {
            uint32_t r0, r1, r2, r3;
            ldsm4(r0, r1, r2, r3, bAddr + p * 16 * PITCH + kk * 32);
            B[2 * p][0] = r0; B[2 * p][1] = r1;
            B[2 * p + 1][0] = r2; B[2 * p + 1][1] = r3;
        }
#pragma unroll
        for (int mt = 0; mt < 2; ++mt)
#pragma unroll
            for (int nt = 0; nt < 8; ++nt)
                mma16816(c[mt][nt], A[mt], B[nt]);
    }
}

// ---------------- prep kernels ----------------------------------------------
__global__ void k_prep_x(const float* __restrict__ x) {
    __shared__ float tile[32][33];
    const int n0 = blockIdx.x * 32, f0 = blockIdx.y * 32;
    const int tx = threadIdx.x, ty = threadIdx.y;
    float v = x[(size_t)(n0 + ty) * 256 + f0 + tx];
    tile[ty][tx] = v;
    __nv_bfloat16 h = __float2bfloat16(v);
    size_t o = (size_t)(n0 + ty) * 512 + 256 + f0 + tx;
    g_nx_hi[o] = h;
    g_nx_lo[o] = __float2bfloat16(v - __bfloat162float(h));
    __syncthreads();
    g_xT[(size_t)(f0 + ty) * NN + n0 + tx] = __float2bfloat16(tile[tx][ty]);
}

__global__ void k_prep_w(const float* __restrict__ w) {
    const int b = blockIdx.x;            // Wt row = k*256 + o
    const int k = b >> 8, o = b & 255;
    const float* src = w + (size_t)k * 512 * 256 + o;
    __nv_bfloat16* dh = g_Wt_hi + (size_t)b * 512;
    __nv_bfloat16* dl = g_Wt_lo + (size_t)b * 512;
    for (int f = threadIdx.x; f < 512; f += 256) {
        float v = src[(size_t)f * 256];
        __nv_bfloat16 h = __float2bfloat16(v);
        dh[f] = h;
        dl[f] = __float2bfloat16(v - __bfloat162float(h));
    }
}

// ---------------- GEMM1: x1 = (adj @ x) / deg --------------------------------
// grid 128 = 64 M-tiles x 2 N-tiles. K = 8192 in 128 chunks of 64.
// A: adj int32 LDG (8x int4/thread) -> exact bf16 STS, 2-stage reg pipeline
//    with a full ~1000-cycle iteration between LDG issue and STS consume.
// B: g_xT bf16 via 4-stage cp.async.
#define PITCH1 144u
#define ASTG1  18432u            // 128 * 144
#define BOFF1  36864u            // 2 A stages
#define BSTG1  18432u            // 4 B stages -> total smem 110592

__device__ __forceinline__ void g1_ldgA(const int* __restrict__ adj, int m0,
                                        int kt, int tid, int4* R) {
    const int4* p = (const int4*)(adj + (size_t)(m0 + (tid >> 1)) * NN +
                                  kt * 64 + (tid & 1) * 32);
#pragma unroll
    for (int j = 0; j < 8; ++j) R[j] = p[j];
}
__device__ __forceinline__ uint32_t pack01(int a, int b) {
    return ((a == 1) ? 0x3F80u : 0u) | ((b == 1) ? 0x3F800000u : 0u);
}
__device__ __forceinline__ void g1_stsA(uint32_t sbase, int s, int tid,
                                        const int4* R, int& cnt) {
    const uint32_t base = sbase + s * ASTG1 + (tid >> 1) * PITCH1 + (tid & 1) * 64;
#pragma unroll
    for (int j = 0; j < 4; ++j) {
        int4 v0 = R[2 * j], v1 = R[2 * j + 1];
        cnt += (v0.x == 1) + (v0.y == 1) + (v0.z == 1) + (v0.w == 1);
        cnt += (v1.x == 1) + (v1.y == 1) + (v1.z == 1) + (v1.w == 1);
        sts16(base + j * 16, pack01(v0.x, v0.y), pack01(v0.z, v0.w),
              pack01(v1.x, v1.y), pack01(v1.z, v1.w));
    }
}
__device__ __forceinline__ void g1_cpB(uint32_t sbase, int s, int kt, int n0,
                                       int tid) {
    const int n = tid >> 1;
    const uint32_t dst = sbase + BOFF1 + s * BSTG1 + n * PITCH1 + (tid & 1) * 64;
    const char* src = (const char*)(g_xT + (size_t)(n0 + n) * NN + kt * 64) +
                      (tid & 1) * 64;
#pragma unroll
    for (int j = 0; j < 4; ++j) cp16(dst + j * 16, src + j * 16);
}

__global__ void __launch_bounds__(256, 1) k_gemm1(const int* __restrict__ adj) {
    extern __shared__ char smem[];
    __shared__ int sdeg[128];
    const uint32_t sbase = smem_u32(smem);
    const int tid = threadIdx.x, lane = tid & 31, wid = tid >> 5;
    const int wm = wid >> 1, wn = wid & 1;
    const int m0 = (blockIdx.x >> 1) * 128, n0 = (blockIdx.x & 1) * 128;
    if (tid < 128) sdeg[tid] = 0;

    int4 Ra[8], Rb[8];
    int cnt = 0;
    g1_ldgA(adj, m0, 0, tid, Ra);
    g1_ldgA(adj, m0, 1, tid, Rb);
    g1_cpB(sbase, 0, 0, n0, tid); cp_commit();
    g1_cpB(sbase, 1, 1, n0, tid); cp_commit();
    g1_cpB(sbase, 2, 2, n0, tid); cp_commit();
    g1_stsA(sbase, 0, tid, Ra, cnt);

    const uint32_t aAddr0 = sbase + (wm * 32 + (lane & 15)) * PITCH1 + (lane >> 4) * 16;
    const uint32_t bAddr0 = sbase + BOFF1 +
        (wn * 64 + ((lane >> 4) << 3) + (lane & 7)) * PITCH1 + ((lane >> 3) & 1) * 16;

    float c[2][8][4] = {};
    for (int it = 0; it < 128; ++it) {
        cp_wait<2>();
        __syncthreads();
        if (it + 2 < 128) g1_ldgA(adj, m0, it + 2, tid, (it & 1) ? Rb : Ra);
        if (it + 3 < 128) g1_cpB(sbase, (it + 3) & 3, it + 3, n0, tid);
        if (it + 1 < 128) g1_stsA(sbase, (it + 1) & 1, tid, ((it + 1) & 1) ? Rb : Ra, cnt);
        cp_commit();
        tile_compute<4, PITCH1>(aAddr0 + (it & 1) * ASTG1,
                                bAddr0 + (it & 3) * BSTG1, c);
    }

    atomicAdd(&sdeg[tid >> 1], cnt);
    __syncthreads();

    // epilogue: /deg, hi/lo bf16 split into g_nx
    const int r = lane >> 2, q = lane & 3;
#pragma unroll
    for (int mt = 0; mt < 2; ++mt) {
        const int lr = wm * 32 + mt * 16 + r;
        const float inv0 = 1.0f / (float)sdeg[lr];
        const float inv1 = 1.0f / (float)sdeg[lr + 8];
        const size_t gm0 = (size_t)(m0 + lr), gm1 = gm0 + 8;
#pragma unroll
        for (int nt = 0; nt < 8; ++nt) {
            const int col = n0 + wn * 64 + nt * 8 + q * 2;
            float v0 = c[mt][nt][0] * inv0, v1 = c[mt][nt][1] * inv0;
            float v2 = c[mt][nt][2] * inv1, v3 = c[mt][nt][3] * inv1;
            __nv_bfloat16 h0 = __float2bfloat16(v0), h1 = __float2bfloat16(v1);
            __nv_bfloat16 h2 = __float2bfloat16(v2), h3 = __float2bfloat16(v3);
            *(uint32_t*)(g_nx_hi + gm0 * 512 + col) =
                ((uint32_t)__bfloat16_as_ushort(h1) << 16) | __bfloat16_as_ushort(h0);
            *(uint32_t*)(g_nx_hi + gm1 * 512 + col) =
                ((uint32_t)__bfloat16_as_ushort(h3) << 16) | __bfloat16_as_ushort(h2);
            __nv_bfloat16 l0 = __float2bfloat16(v0 - __bfloat162float(h0));
            __nv_bfloat16 l1 = __float2bfloat16(v1 - __bfloat162float(h1));
            __nv_bfloat16 l2 = __float2bfloat16(v2 - __bfloat162float(h2));
            __nv_bfloat16 l3 = __float2bfloat16(v3 - __bfloat162float(h3));
            *(uint32_t*)(g_nx_lo + gm0 * 512 + col) =
                ((uint32_t)__bfloat16_as_ushort(l1) << 16) | __bfloat16_as_ushort(l0);
            *(uint32_t*)(g_nx_lo + gm1 * 512 + col) =
                ((uint32_t)__bfloat16_as_ushort(l3) << 16) | __bfloat16_as_ushort(l2);
        }
    }
}

// ---------------- GEMM2: out[k] = nx @ W[k] + bias (3-term bf16 split) ------
// (unchanged from R5 passing version: 66.8us measured)
#define ROWB   80u
#define STG    10240u
#define BOFF   40960u

__device__ __forceinline__ void g2_cp(uint32_t sbase, int s, int it, int m0,
                                      int bn0, int tid) {
    const __nv_bfloat16 *Ap, *Bp;
    int f0;
    if (it < 16)      { Ap = g_nx_hi; Bp = g_Wt_hi; f0 = it * 32; }
    else if (it < 32) { Ap = g_nx_hi; Bp = g_Wt_lo; f0 = (it - 16) * 32; }
    else              { Ap = g_nx_lo; Bp = g_Wt_hi; f0 = 256 + (it - 32) * 32; }
#pragma unroll
    for (int i = 0; i < 2; ++i) {
        int idx = tid + i * 256;
        int rr = idx >> 2, cc = idx & 3;
        cp16(sbase + s * STG + rr * ROWB + cc * 16,
             Ap + (size_t)(m0 + rr) * 512 + f0 + cc * 8);
        cp16(sbase + BOFF + s * STG + rr * ROWB + cc * 16,
             Bp + (size_t)(bn0 + rr) * 512 + f0 + cc * 8);
    }
}

__global__ void __launch_bounds__(256, 2) k_gemm2(const float* __restrict__ bias,
                                                  float* __restrict__ out) {
    extern __shared__ char smem[];
    __shared__ float sbias[128];
    const uint32_t sbase = smem_u32(smem);
    const int tid = threadIdx.x, lane = tid & 31, wid = tid >> 5;
    const int wm = wid >> 1, wn = wid & 1;
    const int bx = blockIdx.x;
    const int m0 = (bx / 6) * 128;
    const int ntile = bx % 6;
    const int kh = ntile >> 1, o0 = (ntile & 1) * 128;
    const int bn0 = kh * 256 + o0;
    if (tid < 128) sbias[tid] = bias[o0 + tid];

    g2_cp(sbase, 0, 0, m0, bn0, tid); cp_commit();
    g2_cp(sbase, 1, 1, m0, bn0, tid); cp_commit();
    g2_cp(sbase, 2, 2, m0, bn0, tid); cp_commit();

    const uint32_t aAddr0 = sbase + (wm * 32 + (lane & 15)) * ROWB + (lane >> 4) * 16;
    const uint32_t bAddr0 = sbase + BOFF +
        (wn * 64 + ((lane >> 4) << 3) + (lane & 7)) * ROWB + ((lane >> 3) & 1) * 16;

    float c[2][8][4] = {};
    for (int it = 0; it < 40; ++it) {
        const int s = it & 3;
        cp_wait<2>();
        __syncthreads();
        if (it + 3 < 40) g2_cp(sbase, (it + 3) & 3, it + 3, m0, bn0, tid);
        cp_commit();
        tile_compute<2, ROWB>(aAddr0 + s * STG, bAddr0 + s * STG, c);
    }

    const int r = lane >> 2, q = lane & 3;
#pragma unroll
    for (int mt = 0; mt < 2; ++mt) {
        const int lr = wm * 32 + mt * 16 + r;
        const size_t gm0 = (size_t)(m0 + lr);
#pragma unroll
        for (int nt = 0; nt < 8; ++nt) {
            const int oc = wn * 64 + nt * 8 + q * 2;
            float2 va = make_float2(c[mt][nt][0] + sbias[oc],
                                    c[mt][nt][1] + sbias[oc + 1]);
            float2 vb = make_float2(c[mt][nt][2] + sbias[oc],
                                    c[mt][nt][3] + sbias[oc + 1]);
            *(float2*)(out + ((size_t)kh * NN + gm0) * 256 + o0 + oc) = va;
            *(float2*)(out + ((size_t)kh * NN + gm0 + 8) * 256 + o0 + oc) = vb;
        }
    }
}

// ---------------- launch -----------------------------------------------------
extern "C" void kernel_launch(void* const* d_in, const int* in_sizes, int n_in,
                              void* d_out, int out_size) {
    const float* x = nullptr;
    const int* adj = nullptr;
    const float* w = nullptr;
    const float* bias = nullptr;
    for (int i = 0; i < n_in; ++i) {
        long sz = in_sizes[i];
        if (sz == (long)NN * 256) x = (const float*)d_in[i];
        else if (sz == (long)NN * NN) adj = (const int*)d_in[i];
        else if (sz == 3L * 512 * 256) w = (const float*)d_in[i];
        else if (sz == 256) bias = (const float*)d_in[i];
    }
    float* out = (float*)d_out;

    cudaFuncSetAttribute(k_gemm1, cudaFuncAttributeMaxDynamicSharedMemorySize, 110592);
    cudaFuncSetAttribute(k_gemm2, cudaFuncAttributeMaxDynamicSharedMemorySize, 81920);

    k_prep_x<<<dim3(256, 8), dim3(32, 32)>>>(x);
    k_prep_w<<<768, 256>>>(w);
    k_gemm1<<<128, 256, 110592>>>(adj);
    k_gemm2<<<384, 256, 81920>>>(bias, out);
}

// round 7
// speedup vs baseline: 1.4810x; 1.4378x over previous
#include <cuda_runtime.h>
#include <cuda_bf16.h>
#include <cstdint>

#define NN 8192

// ---------------- scratch (device globals; no allocations) ------------------
__device__ __align__(128) uint32_t g_adjbits[(size_t)NN * 256];     // 8 MB bitmask
__device__ float g_invdeg[NN];
__device__ __align__(128) __nv_bfloat16 g_xT[(size_t)256 * NN];     // x^T bf16
__device__ __align__(128) __nv_bfloat16 g_nx_hi[(size_t)NN * 512];  // [x1|x] hi
__device__ __align__(128) __nv_bfloat16 g_nx_lo[(size_t)NN * 512];  // [x1|x] lo
__device__ __align__(128) __nv_bfloat16 g_Wt_hi[768 * 512];         // W^T hi
__device__ __align__(128) __nv_bfloat16 g_Wt_lo[768 * 512];         // W^T lo

// ---------------- helpers ----------------------------------------------------
__device__ __forceinline__ uint32_t smem_u32(const void* p) {
    uint32_t a;
    asm("{ .reg .u64 t; cvta.to.shared.u64 t, %1; cvt.u32.u64 %0, t; }"
        : "=r"(a) : "l"(p));
    return a;
}
__device__ __forceinline__ void cp16(uint32_t dst, const void* src) {
    asm volatile("cp.async.cg.shared.global [%0], [%1], 16;" :: "r"(dst), "l"(src));
}
__device__ __forceinline__ void cp_commit() {
    asm volatile("cp.async.commit_group;" ::: "memory");
}
template <int N> __device__ __forceinline__ void cp_wait() {
    asm volatile("cp.async.wait_group %0;" :: "n"(N) : "memory");
}
__device__ __forceinline__ void ldsm4(uint32_t& r0, uint32_t& r1, uint32_t& r2,
                                      uint32_t& r3, uint32_t addr) {
    asm volatile("ldmatrix.sync.aligned.m8n8.x4.shared.b16 {%0,%1,%2,%3}, [%4];"
                 : "=r"(r0), "=r"(r1), "=r"(r2), "=r"(r3) : "r"(addr));
}
__device__ __forceinline__ void mma16816(float* c, const uint32_t* a,
                                         const uint32_t* b) {
    asm volatile(
        "mma.sync.aligned.m16n8k16.row.col.f32.bf16.bf16.f32 "
        "{%0,%1,%2,%3}, {%4,%5,%6,%7}, {%8,%9}, {%0,%1,%2,%3};"
        : "+f"(c[0]), "+f"(c[1]), "+f"(c[2]), "+f"(c[3])
        : "r"(a[0]), "r"(a[1]), "r"(a[2]), "r"(a[3]), "r"(b[0]), "r"(b[1]));
}

// generic warp-tile compute for gemm2 path: 32(M) x 64(N) x (KK*16)(K)
template <int KK, int PITCH>
__device__ __forceinline__ void tile_compute(uint32_t aAddr, uint32_t bAddr,
                                             float (&c)[2][8][4]) {
#pragma unroll
    for (int kk = 0; kk < KK; ++kk) {
        uint32_t A[2][4], B[8][2];
        ldsm4(A[0][0], A[0][1], A[0][2], A[0][3], aAddr + kk * 32);
        ldsm4(A[1][0], A[1][1], A[1][2], A[1][3], aAddr + 16 * PITCH + kk * 32);
#pragma unroll
        for (int p = 0; p < 4; ++p) {
            uint32_t r0, r1, r2, r3;
            ldsm4(r0, r1, r2, r3, bAddr + p * 16 * PITCH + kk * 32);
            B[2 * p][0] = r0; B[2 * p][1] = r1;
            B[2 * p + 1][0] = r2; B[2 * p + 1][1] = r3;
        }
#pragma unroll
        for (int mt = 0; mt < 2; ++mt)
#pragma unroll
            for (int nt = 0; nt < 8; ++nt)
                mma16816(c[mt][nt], A[mt], B[nt]);
    }
}

// ---------------- conv: adj int32 -> bitmask + inv degree --------------------
// g_adjbits[row][W] bit L = (adj[row][W*32+L] == 1)
__global__ void __launch_bounds__(256) k_conv(const int* __restrict__ adj) {
    __shared__ int wsum[8];
    const int row = blockIdx.x;
    const int lane = threadIdx.x & 31, w = threadIdx.x >> 5;
    const int* src = adj + (size_t)row * NN + w * 1024 + lane;
    uint32_t* dst = g_adjbits + (size_t)row * 256 + w * 32;
    int cnt = 0;
#pragma unroll 8
    for (int p = 0; p < 32; ++p) {
        int v = src[p * 32];
        uint32_t b = __ballot_sync(0xFFFFFFFFu, v == 1);
        if (lane == 0) { dst[p] = b; cnt += __popc(b); }
    }
    if (lane == 0) wsum[w] = cnt;
    __syncthreads();
    if (threadIdx.x == 0) {
        int t = 0;
#pragma unroll
        for (int i = 0; i < 8; ++i) t += wsum[i];
        g_invdeg[row] = 1.0f / (float)t;
    }
}

// ---------------- prep kernels ----------------------------------------------
__global__ void k_prep_x(const float* __restrict__ x) {
    __shared__ float tile[32][33];
    const int n0 = blockIdx.x * 32, f0 = blockIdx.y * 32;
    const int tx = threadIdx.x, ty = threadIdx.y;
    float v = x[(size_t)(n0 + ty) * 256 + f0 + tx];
    tile[ty][tx] = v;
    __nv_bfloat16 h = __float2bfloat16(v);
    size_t o = (size_t)(n0 + ty) * 512 + 256 + f0 + tx;
    g_nx_hi[o] = h;
    g_nx_lo[o] = __float2bfloat16(v - __bfloat162float(h));
    __syncthreads();
    g_xT[(size_t)(f0 + ty) * NN + n0 + tx] = __float2bfloat16(tile[tx][ty]);
}

__global__ void k_prep_w(const float* __restrict__ w) {
    const int b = blockIdx.x;            // Wt row = k*256 + o
    const int k = b >> 8, o = b & 255;
    const float* src = w + (size_t)k * 512 * 256 + o;
    __nv_bfloat16* dh = g_Wt_hi + (size_t)b * 512;
    __nv_bfloat16* dl = g_Wt_lo + (size_t)b * 512;
    for (int f = threadIdx.x; f < 512; f += 256) {
        float v = src[(size_t)f * 256];
        __nv_bfloat16 h = __float2bfloat16(v);
        dh[f] = h;
        dl[f] = __float2bfloat16(v - __bfloat162float(h));
    }
}

// ---------------- GEMM1: x1 = (adj @ x) / deg --------------------------------
// grid 128 = 64 M-tiles x 2 N-tiles. K = 8192 in 64 chunks of 128.
// A: bitmask -> register mma fragments (shift/LOP expansion). No A smem.
// B: g_xT bf16 via 4-stage cp.async, pitch 272 (conflict-free ldmatrix).
#define PITCH1 272u
#define BSTG1  34816u            // 128 * 272; 4 stages = 139264 B

__device__ __forceinline__ void g1_cpB(uint32_t sbase, int s, int kc, int n0,
                                       int tid) {
    const int n = tid >> 1, h = tid & 1;
    const uint32_t dst = sbase + s * BSTG1 + n * PITCH1 + h * 128;
    const char* src = (const char*)(g_xT + (size_t)(n0 + n) * NN + kc * 128) +
                      h * 128;
#pragma unroll
    for (int j = 0; j < 8; ++j) cp16(dst + j * 16, src + j * 16);
}

__global__ void __launch_bounds__(256, 1) k_gemm1() {
    extern __shared__ char smem[];
    const uint32_t sbase = smem_u32(smem);
    const int tid = threadIdx.x, lane = tid & 31, wid = tid >> 5;
    const int wm = wid >> 1, wn = wid & 1;
    const int m0 = (blockIdx.x >> 1) * 128, n0 = (blockIdx.x & 1) * 128;

    // bit-row pointers: rows r, r+8, r+16, r+24 of this warp's 32-row block
    const uint32_t* pr[4];
    {
        const uint32_t* base = g_adjbits + (size_t)(m0 + wm * 32 + (lane >> 2)) * 256;
        pr[0] = base; pr[1] = base + 8 * 256;
        pr[2] = base + 16 * 256; pr[3] = base + 24 * 256;
    }

    g1_cpB(sbase, 0, 0, n0, tid); cp_commit();
    g1_cpB(sbase, 1, 1, n0, tid); cp_commit();
    g1_cpB(sbase, 2, 2, n0, tid); cp_commit();

    uint32_t Wc[4][4], Wn[4][4];
#pragma unroll
    for (int rr = 0; rr < 4; ++rr)
#pragma unroll
        for (int j = 0; j < 4; ++j) Wc[rr][j] = pr[rr][j];

    const uint32_t bAddr0 = sbase +
        (wn * 64 + ((lane >> 4) << 3) + (lane & 7)) * PITCH1 + ((lane >> 3) & 1) * 16;
    const int sh0 = (lane & 3) * 2;

    float c[2][8][4] = {};
    for (int it = 0; it < 64; ++it) {
        cp_wait<2>();
        __syncthreads();
        if (it + 3 < 64) g1_cpB(sbase, (it + 3) & 3, it + 3, n0, tid);
        cp_commit();
        if (it + 1 < 64) {
#pragma unroll
            for (int rr = 0; rr < 4; ++rr)
#pragma unroll
                for (int j = 0; j < 4; ++j) Wn[rr][j] = pr[rr][(it + 1) * 4 + j];
        }
        const uint32_t bA = bAddr0 + (it & 3) * BSTG1;
#pragma unroll
        for (int kk = 0; kk < 8; ++kk) {
            uint32_t B[8][2];
#pragma unroll
            for (int p = 0; p < 4; ++p) {
                uint32_t r0, r1, r2, r3;
                ldsm4(r0, r1, r2, r3, bA + p * (16 * PITCH1) + kk * 32);
                B[2 * p][0] = r0; B[2 * p][1] = r1;
                B[2 * p + 1][0] = r2; B[2 * p + 1][1] = r3;
            }
            const int j = kk >> 1;
            const int hs = sh0 + (kk & 1) * 16;
#pragma unroll
            for (int mt = 0; mt < 2; ++mt) {
                uint32_t wr  = Wc[2 * mt][j] >> hs;
                uint32_t wr8 = Wc[2 * mt + 1][j] >> hs;
                uint32_t A[4];
                A[0] = (wr  & 1u) * 0x3F80u | ((wr  >> 1) & 1u) * 0x3F800000u;
                A[1] = (wr8 & 1u) * 0x3F80u | ((wr8 >> 1) & 1u) * 0x3F800000u;
                A[2] = ((wr  >> 8) & 1u) * 0x3F80u | ((wr  >> 9) & 1u) * 0x3F800000u;
                A[3] = ((wr8 >> 8) & 1u) * 0x3F80u | ((wr8 >> 9) & 1u) * 0x3F800000u;
#pragma unroll
                for (int nt = 0; nt < 8; ++nt) mma16816(c[mt][nt], A, B[nt]);
            }
        }
#pragma unroll
        for (int rr = 0; rr < 4; ++rr)
#pragma unroll
            for (int j2 = 0; j2 < 4; ++j2) Wc[rr][j2] = Wn[rr][j2];
    }

    // epilogue: /deg, hi/lo bf16 split into g_nx
    const int r = lane >> 2, q = lane & 3;
#pragma unroll
    for (int mt = 0; mt < 2; ++mt) {
        const int lr = wm * 32 + mt * 16 + r;
        const float inv0 = g_invdeg[m0 + lr];
        const float inv1 = g_invdeg[m0 + lr + 8];
        const size_t gm0 = (size_t)(m0 + lr), gm1 = gm0 + 8;
#pragma unroll
        for (int nt = 0; nt < 8; ++nt) {
            const int col = n0 + wn * 64 + nt * 8 + q * 2;
            float v0 = c[mt][nt][0] * inv0, v1 = c[mt][nt][1] * inv0;
            float v2 = c[mt][nt][2] * inv1, v3 = c[mt][nt][3] * inv1;
            __nv_bfloat16 h0 = __float2bfloat16(v0), h1 = __float2bfloat16(v1);
            __nv_bfloat16 h2 = __float2bfloat16(v2), h3 = __float2bfloat16(v3);
            *(uint32_t*)(g_nx_hi + gm0 * 512 + col) =
                ((uint32_t)__bfloat16_as_ushort(h1) << 16) | __bfloat16_as_ushort(h0);
            *(uint32_t*)(g_nx_hi + gm1 * 512 + col) =
                ((uint32_t)__bfloat16_as_ushort(h3) << 16) | __bfloat16_as_ushort(h2);
            __nv_bfloat16 l0 = __float2bfloat16(v0 - __bfloat162float(h0));
            __nv_bfloat16 l1 = __float2bfloat16(v1 - __bfloat162float(h1));
            __nv_bfloat16 l2 = __float2bfloat16(v2 - __bfloat162float(h2));
            __nv_bfloat16 l3 = __float2bfloat16(v3 - __bfloat162float(h3));
            *(uint32_t*)(g_nx_lo + gm0 * 512 + col) =
                ((uint32_t)__bfloat16_as_ushort(l1) << 16) | __bfloat16_as_ushort(l0);
            *(uint32_t*)(g_nx_lo + gm1 * 512 + col) =
                ((uint32_t)__bfloat16_as_ushort(l3) << 16) | __bfloat16_as_ushort(l2);
        }
    }
}

// ---------------- GEMM2: out[k] = nx @ W[k] + bias (3-term bf16 split) ------
// (unchanged from R5/R6 passing version: 66.6us measured)
#define ROWB   80u
#define STG    10240u
#define BOFF   40960u

__device__ __forceinline__ void g2_cp(uint32_t sbase, int s, int it, int m0,
                                      int bn0, int tid) {
    const __nv_bfloat16 *Ap, *Bp;
    int f0;
    if (it < 16)      { Ap = g_nx_hi; Bp = g_Wt_hi; f0 = it * 32; }
    else if (it < 32) { Ap = g_nx_hi; Bp = g_Wt_lo; f0 = (it - 16) * 32; }
    else              { Ap = g_nx_lo; Bp = g_Wt_hi; f0 = 256 + (it - 32) * 32; }
#pragma unroll
    for (int i = 0; i < 2; ++i) {
        int idx = tid + i * 256;
        int rr = idx >> 2, cc = idx & 3;
        cp16(sbase + s * STG + rr * ROWB + cc * 16,
             Ap + (size_t)(m0 + rr) * 512 + f0 + cc * 8);
        cp16(sbase + BOFF + s * STG + rr * ROWB + cc * 16,
             Bp + (size_t)(bn0 + rr) * 512 + f0 + cc * 8);
    }
}

__global__ void __launch_bounds__(256, 2) k_gemm2(const float* __restrict__ bias,
                                                  float* __restrict__ out) {
    extern __shared__ char smem[];
    __shared__ float sbias[128];
    const uint32_t sbase = smem_u32(smem);
    const int tid = threadIdx.x, lane = tid & 31, wid = tid >> 5;
    const int wm = wid >> 1, wn = wid & 1;
    const int bx = blockIdx.x;
    const int m0 = (bx / 6) * 128;
    const int ntile = bx % 6;
    const int kh = ntile >> 1, o0 = (ntile & 1) * 128;
    const int bn0 = kh * 256 + o0;
    if (tid < 128) sbias[tid] = bias[o0 + tid];

    g2_cp(sbase, 0, 0, m0, bn0, tid); cp_commit();
    g2_cp(sbase, 1, 1, m0, bn0, tid); cp_commit();
    g2_cp(sbase, 2, 2, m0, bn0, tid); cp_commit();

    const uint32_t aAddr0 = sbase + (wm * 32 + (lane & 15)) * ROWB + (lane >> 4) * 16;
    const uint32_t bAddr0 = sbase + BOFF +
        (wn * 64 + ((lane >> 4) << 3) + (lane & 7)) * ROWB + ((lane >> 3) & 1) * 16;

    float c[2][8][4] = {};
    for (int it = 0; it < 40; ++it) {
        const int s = it & 3;
        cp_wait<2>();
        __syncthreads();
        if (it + 3 < 40) g2_cp(sbase, (it + 3) & 3, it + 3, m0, bn0, tid);
        cp_commit();
        tile_compute<2, ROWB>(aAddr0 + s * STG, bAddr0 + s * STG, c);
    }

    const int r = lane >> 2, q = lane & 3;
#pragma unroll
    for (int mt = 0; mt < 2; ++mt) {
        const int lr = wm * 32 + mt * 16 + r;
        const size_t gm0 = (size_t)(m0 + lr);
#pragma unroll
        for (int nt = 0; nt < 8; ++nt) {
            const int oc = wn * 64 + nt * 8 + q * 2;
            float2 va = make_float2(c[mt][nt][0] + sbias[oc],
                                    c[mt][nt][1] + sbias[oc + 1]);
            float2 vb = make_float2(c[mt][nt][2] + sbias[oc],
                                    c[mt][nt][3] + sbias[oc + 1]);
            *(float2*)(out + ((size_t)kh * NN + gm0) * 256 + o0 + oc) = va;
            *(float2*)(out + ((size_t)kh * NN + gm0 + 8) * 256 + o0 + oc) = vb;
        }
    }
}

// ---------------- launch -----------------------------------------------------
extern "C" void kernel_launch(void* const* d_in, const int* in_sizes, int n_in,
                              void* d_out, int out_size) {
    const float* x = nullptr;
    const int* adj = nullptr;
    const float* w = nullptr;
    const float* bias = nullptr;
    for (int i = 0; i < n_in; ++i) {
        long sz = in_sizes[i];
        if (sz == (long)NN * 256) x = (const float*)d_in[i];
        else if (sz == (long)NN * NN) adj = (const int*)d_in[i];
        else if (sz == 3L * 512 * 256) w = (const float*)d_in[i];
        else if (sz == 256) bias = (const float*)d_in[i];
    }
    float* out = (float*)d_out;

    cudaFuncSetAttribute(k_gemm1, cudaFuncAttributeMaxDynamicSharedMemorySize, 139264);
    cudaFuncSetAttribute(k_gemm2, cudaFuncAttributeMaxDynamicSharedMemorySize, 81920);

    k_prep_x<<<dim3(256, 8), dim3(32, 32)>>>(x);
    k_prep_w<<<768, 256>>>(w);
    k_conv<<<NN, 256>>>(adj);
    k_gemm1<<<128, 256, 139264>>>();
    k_gemm2<<<384, 256, 81920>>>(bias, out);
}